// round 13
// baseline (speedup 1.0000x reference)
#include <cuda_runtime.h>

#define BIN 256
#define IM 256
#define NPIX (IM * IM)          // 65536
#define NBLOCKS 512
#define NTHREADS 256            // 131072 threads, all co-resident

#define NDEAD (2 * (BIN * BIN - 128 * 128))   // 98304 zero outputs
#define NLIVE2 (2 * 128 * 128 / 2)            // 16384 float2 live cells

// Scratch: 4 histograms ({inp,ref} x {b0,b1}) of 256x256 float = 1 MB.
// Full-size layout (R7-proven; compact layout regressed in R8 via LTS-hash
// concentration). Zero-initialized at module load; live cells re-zeroed in
// phase B after reading, so every graph replay starts from zeros.
__device__ float g_hist[4 * BIN * BIN];

// Monotonic barrier counter (never reset -> graph-replay safe: each run
// consumes exactly NBLOCKS increments; epoch = my/NBLOCKS uniform per run).
__device__ unsigned long long g_bar;

// Triangular-kernel weight, numerics matching the reference exactly:
//   bias_k = 1 - 2k/256 (exact dyadic), a1 = u + bias_k, w = relu(1 - |a1|*255)
__device__ __forceinline__ float tri_w(float u, int k) {
    float a1 = u + (1.0f - (float)k * 0.0078125f);
    return fmaxf(0.0f, 1.0f - fabsf(a1) * 255.0f);
}

// Scatter one pixel (channel values xa, xb) into histogram H (256x256).
// At most 2 bins active per axis, usually exactly 1 (support 1/255 vs
// half-pitch 1/256) -> ~1.3 atomics per pixel thanks to the predicates.
__device__ __forceinline__ void scatter_pixel(float xa, float xb,
                                              float* __restrict__ H) {
    float ua = (xa + 1.0f) * 0.5f;
    float ub = (xb + 1.0f) * 0.5f;

    // t = 128u+128 in [128,256) (positive) -> int truncation == floor
    int ka = (int)(ua * 128.0f + 128.0f);
    int kb = (int)(ub * 128.0f + 128.0f);

    float wa0 = tri_w(ua, ka);
    float wa1 = tri_w(ua, ka + 1);
    float wb0 = tri_w(ub, kb);
    float wb1 = tri_w(ub, kb + 1);

    bool a0 = wa0 > 0.0f;
    bool a1 = wa1 > 0.0f && (ka + 1) < BIN;
    bool b0 = wb0 > 0.0f;
    bool b1 = wb1 > 0.0f && (kb + 1) < BIN;

    float* row0 = H + kb * BIN;
    if (b0) {
        if (a0) atomicAdd(row0 + ka,     wb0 * wa0);
        if (a1) atomicAdd(row0 + ka + 1, wb0 * wa1);
    }
    if (b1) {
        float* row1 = row0 + BIN;
        if (a0) atomicAdd(row1 + ka,     wb1 * wa0);
        if (a1) atomicAdd(row1 + ka + 1, wb1 * wa1);
    }
}

__global__ void __launch_bounds__(NTHREADS)
fused_kernel(const float* __restrict__ inp,
             const float* __restrict__ ref,
             float* __restrict__ out) {
    int idx = blockIdx.x * NTHREADS + threadIdx.x;   // 0 .. 131071

    // ------- Dead-region zero stores FIRST: depend on nothing ------------
    // Bins j<128 or r<128 are never touched (u in [0,1) -> k in [128,255]):
    // those outputs are exactly Huber(0-0)=0. Issuing these STGs at the top
    // hides them under the input-load DRAM latency of phase A.
    if (idx < NDEAD) {
        int b = idx / (NDEAD / 2);            // 49152 dead per batch
        int e = idx - b * (NDEAD / 2);
        int o;
        if (e < 128 * BIN) {                  // rows j in [0,128): all r
            o = e;                            // j = e>>8, r = e&255
        } else {                              // rows j in [128,256): r<128
            int e2 = e - 128 * BIN;
            o = (128 + (e2 >> 7)) * BIN + (e2 & 127);
        }
        out[b * BIN * BIN + o] = 0.0f;
    }

    // ---------------- Phase A: scatter (one 2-pixel group / thread) --------
    // idx -> (t, b, q): t = image, b = batch, q = float2 group (2 pixels)
    {
        int t = idx >> 16;                 // 0=inp, 1=ref
        int b = (idx >> 15) & 1;           // batch
        int q = idx & (NPIX / 2 - 1);      // float2 index within plane

        const float* img = (t == 0) ? inp : ref;
        const float2* cha = reinterpret_cast<const float2*>(
            img + (b * 2 + 0) * NPIX);     // ch0 -> r axis
        const float2* chb = reinterpret_cast<const float2*>(
            img + (b * 2 + 1) * NPIX);     // ch1 -> j axis

        float2 va = cha[q];
        float2 vb = chb[q];

        float* H = g_hist + (t * 2 + b) * BIN * BIN;
        scatter_pixel(va.x, vb.x, H);
        scatter_pixel(va.y, vb.y, H);
    }

    // ---------------- Inter-block barrier (epoch counter) ----------------
    __threadfence();     // my REDs globally visible before arrival
    __syncthreads();     // whole block done before block arrives
    if (threadIdx.x == 0) {
        unsigned long long my = atomicAdd(&g_bar, 1ULL);
        unsigned long long target =
            (my / (unsigned long long)NBLOCKS + 1ULL) *
            (unsigned long long)NBLOCKS;
        unsigned long long v;
        do {
            asm volatile("ld.relaxed.gpu.u64 %0, [%1];"
                         : "=l"(v) : "l"(&g_bar) : "memory");
        } while (v < target);
        asm volatile("fence.acq_rel.gpu;" ::: "memory");
    }
    __syncthreads();

    // ---------------- Phase B: live quadrant, float2-vectorized ----------
    // 32768 live cells as 16384 float2: j,r in [128,256), b in {0,1}.
    // Live rows are 128 contiguous floats -> float2 accesses stay aligned
    // and coalesced. Load both hists, re-zero for next replay, Huber, store.
    if (idx < NLIVE2) {
        int b   = idx >> 13;                  // 8192 float2 per batch
        int ci  = idx & 8191;
        int j   = 128 + (ci >> 6);            // 64 float2 per live row
        int r   = 128 + ((ci & 63) << 1);
        int jr  = j * BIN + r;

        float2* Hi = reinterpret_cast<float2*>(
            g_hist + (0 * 2 + b) * BIN * BIN + jr);
        float2* Hg = reinterpret_cast<float2*>(
            g_hist + (1 * 2 + b) * BIN * BIN + jr);

        float2 hi = *Hi;
        float2 hg = *Hg;
        const float2 z = make_float2(0.0f, 0.0f);
        *Hi = z;
        *Hg = z;

        const float inv = 1.0f / (float)NPIX;
        float2 v;
        float m;
        m = fabsf(hi.x - hg.x) * inv;
        v.x = (m < 0.01f) ? 50.0f * m * m : m - 0.005f;
        m = fabsf(hi.y - hg.y) * inv;
        v.y = (m < 0.01f) ? 50.0f * m * m : m - 0.005f;

        *reinterpret_cast<float2*>(out + b * BIN * BIN + jr) = v;
    }
}

// ---------------------------------------------------------------------------
extern "C" void kernel_launch(void* const* d_in, const int* in_sizes, int n_in,
                              void* d_out, int out_size) {
    const float* inp = (const float*)d_in[0];
    const float* ref = (const float*)d_in[1];
    float* out = (float*)d_out;

    fused_kernel<<<NBLOCKS, NTHREADS>>>(inp, ref, out);
}

// round 14
// speedup vs baseline: 1.1910x; 1.1910x over previous
#include <cuda_runtime.h>

#define BIN 256
#define IM 256
#define NPIX (IM * IM)          // 65536
#define NBLOCKS 512
#define NTHREADS 256            // 131072 threads, all co-resident

#define NDEAD (2 * (BIN * BIN - 128 * 128))   // 98304 zero outputs
#define NLIVE (2 * 128 * 128)                 // 32768 live outputs

// Scratch: 4 histograms ({inp,ref} x {b0,b1}) of 256x256 float = 1 MB.
// Full-size layout (R7-proven; compact layout regressed in R8 via LTS-hash
// concentration). Zero-initialized at module load; live cells re-zeroed in
// phase B after reading, so every graph replay starts from zeros.
__device__ float g_hist[4 * BIN * BIN];

// Monotonic barrier counter (never reset -> graph-replay safe: each run
// consumes exactly NBLOCKS increments; epoch = my/NBLOCKS uniform per run).
__device__ unsigned long long g_bar;

// Triangular-kernel weight, numerics matching the reference exactly:
//   bias_k = 1 - 2k/256 (exact dyadic), a1 = u + bias_k, w = relu(1 - |a1|*255)
__device__ __forceinline__ float tri_w(float u, int k) {
    float a1 = u + (1.0f - (float)k * 0.0078125f);
    return fmaxf(0.0f, 1.0f - fabsf(a1) * 255.0f);
}

// Scatter one pixel (channel values xa, xb) into histogram H (256x256).
// At most 2 bins active per axis, usually exactly 1 (support 1/255 vs
// half-pitch 1/256) -> ~1.3 atomics per pixel thanks to the predicates.
__device__ __forceinline__ void scatter_pixel(float xa, float xb,
                                              float* __restrict__ H) {
    float ua = (xa + 1.0f) * 0.5f;
    float ub = (xb + 1.0f) * 0.5f;

    // t = 128u+128 in [128,256) (positive) -> int truncation == floor
    int ka = (int)(ua * 128.0f + 128.0f);
    int kb = (int)(ub * 128.0f + 128.0f);

    float wa0 = tri_w(ua, ka);
    float wa1 = tri_w(ua, ka + 1);
    float wb0 = tri_w(ub, kb);
    float wb1 = tri_w(ub, kb + 1);

    bool a0 = wa0 > 0.0f;
    bool a1 = wa1 > 0.0f && (ka + 1) < BIN;
    bool b0 = wb0 > 0.0f;
    bool b1 = wb1 > 0.0f && (kb + 1) < BIN;

    float* row0 = H + kb * BIN;
    if (b0) {
        if (a0) atomicAdd(row0 + ka,     wb0 * wa0);
        if (a1) atomicAdd(row0 + ka + 1, wb0 * wa1);
    }
    if (b1) {
        float* row1 = row0 + BIN;
        if (a0) atomicAdd(row1 + ka,     wb1 * wa0);
        if (a1) atomicAdd(row1 + ka + 1, wb1 * wa1);
    }
}

__global__ void __launch_bounds__(NTHREADS)
fused_kernel(const float* __restrict__ inp,
             const float* __restrict__ ref,
             float* __restrict__ out) {
    int idx = blockIdx.x * NTHREADS + threadIdx.x;   // 0 .. 131071

    // ---- Issue order: input LDGs first, independent STGs in their shadow,
    //      then the dependent scatter math + atomics. ----

    // (1) Input loads: idx -> (t, b, q), one float2 group (2 pixels).
    int t = idx >> 16;                 // 0=inp, 1=ref
    int b = (idx >> 15) & 1;           // batch
    int q = idx & (NPIX / 2 - 1);      // float2 index within plane

    const float* img = (t == 0) ? inp : ref;
    const float2* cha = reinterpret_cast<const float2*>(
        img + (b * 2 + 0) * NPIX);     // ch0 -> r axis
    const float2* chb = reinterpret_cast<const float2*>(
        img + (b * 2 + 1) * NPIX);     // ch1 -> j axis

    float2 va = cha[q];
    float2 vb = chb[q];

    // (2) Dead-region zero stores: independent of the loads above; issued
    // while the LDGs are in flight (~577 cyc DRAM). Bins j<128 or r<128
    // are never touched by scatter (u in [0,1) -> k in [128,255]); their
    // outputs are exactly Huber(0-0)=0.
    if (idx < NDEAD) {
        int bb = idx / (NDEAD / 2);           // 49152 dead per batch
        int e = idx - bb * (NDEAD / 2);
        int o;
        if (e < 128 * BIN) {                  // rows j in [0,128): all r
            o = e;                            // j = e>>8, r = e&255
        } else {                              // rows j in [128,256): r<128
            int e2 = e - 128 * BIN;
            o = (128 + (e2 >> 7)) * BIN + (e2 & 127);
        }
        out[bb * BIN * BIN + o] = 0.0f;
    }

    // (3) Scatter: consumes the loaded values.
    {
        float* H = g_hist + (t * 2 + b) * BIN * BIN;
        scatter_pixel(va.x, vb.x, H);
        scatter_pixel(va.y, vb.y, H);
    }

    // ---------------- Inter-block barrier (epoch counter) ----------------
    __threadfence();     // my REDs globally visible before arrival
    __syncthreads();     // whole block done before block arrives
    if (threadIdx.x == 0) {
        unsigned long long my = atomicAdd(&g_bar, 1ULL);
        unsigned long long target =
            (my / (unsigned long long)NBLOCKS + 1ULL) *
            (unsigned long long)NBLOCKS;
        unsigned long long v;
        do {
            asm volatile("ld.relaxed.gpu.u64 %0, [%1];"
                         : "=l"(v) : "l"(&g_bar) : "memory");
        } while (v < target);
        asm volatile("fence.acq_rel.gpu;" ::: "memory");
    }
    __syncthreads();

    // ---------------- Phase B: live quadrant only (scalar, R10-proven) ----
    // 32768 live cells: j,r in [128,256), b in {0,1}. Load both hists,
    // re-zero for the next replay, Huber, store. Coalesced (warp = 32
    // consecutive r within a 128-run).
    if (idx < NLIVE) {
        int bb = idx >> 14;                   // 16384 live per batch
        int ci = idx & 16383;
        int j  = 128 + (ci >> 7);
        int r  = 128 + (ci & 127);
        int jr = j * BIN + r;

        int oi = (0 * 2 + bb) * BIN * BIN + jr;   // inp hist cell
        int gi = (1 * 2 + bb) * BIN * BIN + jr;   // ref hist cell
        float hi = g_hist[oi];
        float hg = g_hist[gi];
        g_hist[oi] = 0.0f;
        g_hist[gi] = 0.0f;

        const float inv = 1.0f / (float)NPIX;
        float m = fabsf(hi - hg) * inv;
        out[bb * BIN * BIN + jr] =
            (m < 0.01f) ? 50.0f * m * m : m - 0.005f;
    }
}

// ---------------------------------------------------------------------------
extern "C" void kernel_launch(void* const* d_in, const int* in_sizes, int n_in,
                              void* d_out, int out_size) {
    const float* inp = (const float*)d_in[0];
    const float* ref = (const float*)d_in[1];
    float* out = (float*)d_out;

    fused_kernel<<<NBLOCKS, NTHREADS>>>(inp, ref, out);
}